// round 10
// baseline (speedup 1.0000x reference)
#include <cuda_runtime.h>
#include <cstdint>

#define BATCH   16384
#define SEQ_L   64
#define T_STEPS 32
#define NH      128
#define TPC     64
#define NCTA    (BATCH / TPC)   // 256
#define THREADS 512

// ---------------- smem layout (bytes) ----------------
#define S_BW   0                 // packed B-frags [8kc][8cg][2f][32lane][4g] uint2 = 131072
#define S_A0   131072            // h tile parity 0, bf16 [64][136]                 = 17408
#define S_A1   148480            // h tile parity 1                                 = 17408
#define S_XI   165888            // float4 xi [4 v][128 j]                          = 8192
#define S_P    174080            // uint8 patch idx [32][64]                        = 2048
#define S_PART 176128            // f32 partials [2 par][8 cg][64 row][4 o]         = 16384
#define S_W2T  192512            // float4 w2T [128 col][4 o]                       = 2048
#define SMEM_TOTAL 194560
#define A_BUFSZ 17408

// ---------------- helpers ----------------
__device__ __forceinline__ uint32_t s2u(const void* p) {
    uint32_t a;
    asm("{ .reg .u64 t; cvta.to.shared.u64 t, %1; cvt.u32.u64 %0, t; }" : "=r"(a) : "l"(p));
    return a;
}
__device__ __forceinline__ uint32_t bf2(float lo, float hi) {
    uint32_t r; asm("cvt.rn.bf16x2.f32 %0, %1, %2;" : "=r"(r) : "f"(hi), "f"(lo)); return r;
}
__device__ __forceinline__ void ldm4(uint32_t* a, uint32_t addr) {
    asm volatile("ldmatrix.sync.aligned.m8n8.x4.shared.b16 {%0,%1,%2,%3}, [%4];"
        : "=r"(a[0]), "=r"(a[1]), "=r"(a[2]), "=r"(a[3]) : "r"(addr));
}
__device__ __forceinline__ void mma16(float* d, const uint32_t* a, uint32_t b0, uint32_t b1) {
    asm volatile("mma.sync.aligned.m16n8k16.row.col.f32.bf16.bf16.f32 "
        "{%0,%1,%2,%3},{%4,%5,%6,%7},{%8,%9},{%0,%1,%2,%3};"
        : "+f"(d[0]), "+f"(d[1]), "+f"(d[2]), "+f"(d[3])
        : "r"(a[0]), "r"(a[1]), "r"(a[2]), "r"(a[3]), "r"(b0), "r"(b1));
}
__device__ __forceinline__ float tanha(float x) {
    float y; asm("tanh.approx.f32 %0,%1;" : "=f"(y) : "f"(x)); return y;
}
__device__ __forceinline__ float siga(float x) {
    return fmaf(0.5f, tanha(0.5f * x), 0.5f);
}

// ============================================================================
// Fused PRNN. 64 samples/CTA, 512 threads (16 warps).
// Warp = (cg 0..7, rh 0..1): owns rows [32rh,32rh+32) x cols [16cg,16cg+16).
// 64 fp32 accums/thread -> ~124 regs -> 4 warps/SMSP.
// One barrier/iter (double-buffered A). Packed B frags: gates+hid contiguous.
// ============================================================================
__global__ __launch_bounds__(THREADS, 1) void prnn_kernel(
    const float* __restrict__ x, const float* __restrict__ w_ih,
    const float* __restrict__ w_hh, const float* __restrict__ b_ih,
    const float* __restrict__ b_hh, const float* __restrict__ w1,
    const float* __restrict__ b1, const float* __restrict__ w2,
    const float* __restrict__ b2, float* __restrict__ out)
{
    extern __shared__ char sm[];
    float4* sXI  = (float4*)(sm + S_XI);
    unsigned char* sP = (unsigned char*)(sm + S_P);
    float*  sPart = (float*)(sm + S_PART);
    float4* sW2T = (float4*)(sm + S_W2T);

    const int tid = threadIdx.x;
    const int wid = tid >> 5, lane = tid & 31;
    const int rg = lane >> 2, c4 = lane & 3;
    const int cg = wid & 7, rh = wid >> 3;
    const int j0 = cg * 16;
    const int rbase = rh * 32;
    const int bBase = blockIdx.x * TPC;
    const uint32_t saB = s2u(sm + S_A0);

    // ---- stage packed B-frags: i = (((kc*8+cg)*2+f)*32+lane)*4 + g ----
    for (int i = tid; i < 16384; i += THREADS) {
        int g = i & 3, ln = (i >> 2) & 31, f = (i >> 7) & 1;
        int cgs = (i >> 8) & 7, kc = i >> 11;
        int nrow = (cgs * 2 + f) * 8 + (ln >> 2);
        const float* wr = (g < 3) ? (w_hh + (g * NH + nrow) * NH) : (w1 + nrow * NH);
        wr += kc * 16 + (ln & 3) * 2;
        ((uint2*)(sm + S_BW))[i] = make_uint2(bf2(wr[0], wr[1]), bf2(wr[8], wr[9]));
    }
    // ---- xi table (R7-identical staging math): [v][j] = {xi_r, xi_z, xi_n, b_hh_n} ----
    for (int i = tid; i < 4 * NH; i += THREADS) {
        int v = i >> 7, j = i & 127;
        float xr = b_ih[j] + b_hh[j];
        float xz = b_ih[NH + j] + b_hh[NH + j];
        float xn = b_ih[2 * NH + j];
        if (v & 1) { xr += w_ih[j * 2]; xz += w_ih[(NH + j) * 2]; xn += w_ih[(2 * NH + j) * 2]; }
        if (v & 2) { xr += w_ih[j * 2 + 1]; xz += w_ih[(NH + j) * 2 + 1]; xn += w_ih[(2 * NH + j) * 2 + 1]; }
        sXI[i] = make_float4(xr, xz, xn, b_hh[2 * NH + j]);
    }
    // ---- w2 transposed table ----
    for (int i = tid; i < NH; i += THREADS)
        sW2T[i] = make_float4(w2[i], w2[NH + i], w2[2 * NH + i], w2[3 * NH + i]);
    // ---- patch indices ----
    for (int i = tid; i < T_STEPS * TPC; i += THREADS) {
        int t = i >> 6, s = i & 63;
        const float* xb = x + (size_t)(bBase + s) * SEQ_L + 2 * t;
        sP[i] = (unsigned char)((xb[0] != 0.0f ? 1 : 0) | (xb[1] != 0.0f ? 2 : 0));
    }
    // ---- zero both A buffers ----
    for (int i = tid; i < 2 * A_BUFSZ / 4; i += THREADS) ((uint32_t*)(sm + S_A0))[i] = 0u;

    // ---- per-thread b1 (4 cols: ci = f*2+lo -> j0 + f*8 + 2c4 + lo) ----
    float b1c[4];
    #pragma unroll
    for (int ci = 0; ci < 4; ci++)
        b1c[ci] = b1[j0 + (ci >> 1) * 8 + 2 * c4 + (ci & 1)];
    const float b2r = b2[tid & 3];

    float hp[2][2][4];
    #pragma unroll
    for (int m = 0; m < 2; m++)
        #pragma unroll
        for (int f = 0; f < 2; f++)
            #pragma unroll
            for (int e = 0; e < 4; e++) hp[m][f][e] = 0.0f;
    float acc = 0.0f;

    const uint32_t lmBase = saB + (uint32_t)(rbase + (lane & 15)) * 272 + (uint32_t)(lane >> 4) * 16;

    for (int t = 0; t <= T_STEPS + 1; t++) {
        __syncthreads();   // sA[t&1] and sPart[(t-1)&1] complete

        const uint32_t abuf = (uint32_t)(t & 1) * A_BUFSZ;

        // ---------- merged MMA: gates (step t) + hid (step t-1) ----------
        float aR[2][2][4], aZ[2][2][4], aN[2][2][4], aH[2][2][4];
        #pragma unroll
        for (int m = 0; m < 2; m++)
            #pragma unroll
            for (int f = 0; f < 2; f++)
                #pragma unroll
                for (int e = 0; e < 4; e++) {
                    aR[m][f][e] = 0.f; aZ[m][f][e] = 0.f; aN[m][f][e] = 0.f; aH[m][f][e] = 0.f;
                }
        if (t <= T_STEPS) {
            #pragma unroll
            for (int kc = 0; kc < 8; kc++) {
                uint32_t A[2][4];
                #pragma unroll
                for (int m = 0; m < 2; m++) ldm4(A[m], lmBase + abuf + m * 16 * 272 + kc * 32);
                #pragma unroll
                for (int f = 0; f < 2; f++) {
                    const uint4* bp = (const uint4*)(sm + S_BW +
                        ((size_t)(((kc * 8 + cg) * 2 + f) * 32 + lane)) * 32);
                    uint4 B01 = bp[0];          // r frag (x,y), z frag (z,w)
                    uint4 B23 = bp[1];          // n frag (x,y), hid frag (z,w)
                    if (t < T_STEPS) {
                        #pragma unroll
                        for (int m = 0; m < 2; m++) {
                            mma16(aR[m][f], A[m], B01.x, B01.y);
                            mma16(aZ[m][f], A[m], B01.z, B01.w);
                            mma16(aN[m][f], A[m], B23.x, B23.y);
                        }
                    }
                    if (t >= 1) {
                        #pragma unroll
                        for (int m = 0; m < 2; m++) mma16(aH[m][f], A[m], B23.z, B23.w);
                    }
                }
            }
        }

        // ---------- logits + logsumexp for step t-2 (under MMA shadow) ----------
        if (t >= 2 && tid < 256) {
            int row = tid >> 2;
            const float* pb = sPart + (size_t)((t - 1) & 1) * 2048 + row * 4 + (tid & 3);
            float l = b2r;
            #pragma unroll
            for (int w = 0; w < 8; w++) l += pb[w * 256];
            float m1 = fmaxf(l, __shfl_xor_sync(0xffffffffu, l, 1));
            float mx = fmaxf(m1, __shfl_xor_sync(0xffffffffu, m1, 2));
            float e = __expf(l - mx);
            float s = e + __shfl_xor_sync(0xffffffffu, e, 1);
            s += __shfl_xor_sync(0xffffffffu, s, 2);
            float lse = mx + __logf(s);
            int idx = sP[(t - 2) * TPC + row];
            float lpick = __shfl_sync(0xffffffffu, l, (lane & ~3) | idx);
            if ((tid & 3) == 0) acc += lpick - lse;
        }

        // ---------- gate epilogue: h_t -> sA[(t+1)&1] ----------
        if (t < T_STEPS) {
            const uint32_t wbuf = (uint32_t)((t + 1) & 1) * A_BUFSZ;
            #pragma unroll
            for (int m = 0; m < 2; m++)
                #pragma unroll
                for (int rr = 0; rr < 2; rr++) {
                    int row = rbase + m * 16 + rg + rr * 8;
                    int v = (t > 0) ? sP[(t - 1) * TPC + row] : 0;
                    #pragma unroll
                    for (int f = 0; f < 2; f++) {
                        int col0 = j0 + f * 8 + 2 * c4;
                        int e0 = rr * 2, e1 = rr * 2 + 1;
                        float4 xa = sXI[v * NH + col0];
                        float4 xb = sXI[v * NH + col0 + 1];
                        float r0 = siga(aR[m][f][e0] + xa.x);
                        float r1 = siga(aR[m][f][e1] + xb.x);
                        float z0 = siga(aZ[m][f][e0] + xa.y);
                        float z1 = siga(aZ[m][f][e1] + xb.y);
                        float n0 = tanha(xa.z + r0 * (aN[m][f][e0] + xa.w));
                        float n1 = tanha(xb.z + r1 * (aN[m][f][e1] + xb.w));
                        float h0 = n0 + z0 * (hp[m][f][e0] - n0);
                        float h1 = n1 + z1 * (hp[m][f][e1] - n1);
                        hp[m][f][e0] = h0; hp[m][f][e1] = h1;
                        *(uint32_t*)(sm + S_A0 + wbuf + row * 272 + col0 * 2) = bf2(h0, h1);
                    }
                }
        }

        // ---------- head partials for step t-1 -> sPart[t&1] ----------
        if (t >= 1 && t <= T_STEPS) {
            float4 wci[4];
            #pragma unroll
            for (int ci = 0; ci < 4; ci++)
                wci[ci] = sW2T[j0 + (ci >> 1) * 8 + 2 * c4 + (ci & 1)];
            float p[4][4];
            #pragma unroll
            for (int q = 0; q < 4; q++)
                #pragma unroll
                for (int o = 0; o < 4; o++) p[q][o] = 0.0f;
            #pragma unroll
            for (int m = 0; m < 2; m++)
                #pragma unroll
                for (int f = 0; f < 2; f++)
                    #pragma unroll
                    for (int e = 0; e < 4; e++) {
                        int ci = f * 2 + (e & 1);
                        int q = m * 2 + (e >> 1);
                        float hid = fmaxf(aH[m][f][e] + b1c[ci], 0.0f);
                        p[q][0] = fmaf(hid, wci[ci].x, p[q][0]);
                        p[q][1] = fmaf(hid, wci[ci].y, p[q][1]);
                        p[q][2] = fmaf(hid, wci[ci].z, p[q][2]);
                        p[q][3] = fmaf(hid, wci[ci].w, p[q][3]);
                    }
            #pragma unroll
            for (int q = 0; q < 4; q++)
                #pragma unroll
                for (int o = 0; o < 4; o++) {
                    float v = p[q][o];
                    v += __shfl_xor_sync(0xffffffffu, v, 1);
                    v += __shfl_xor_sync(0xffffffffu, v, 2);
                    p[q][o] = v;
                }
            if (c4 == 0) {
                float4* dst = (float4*)(sPart + (size_t)(t & 1) * 2048 + cg * 256);
                #pragma unroll
                for (int q = 0; q < 4; q++) {
                    int row = rbase + (q >> 1) * 16 + rg + (q & 1) * 8;
                    dst[row] = make_float4(p[q][0], p[q][1], p[q][2], p[q][3]);
                }
            }
        }
    }

    if (tid < 256 && (tid & 3) == 0) out[bBase + (tid >> 2)] = acc;
}

extern "C" void kernel_launch(void* const* d_in, const int* in_sizes, int n_in,
                              void* d_out, int out_size) {
    const float* x    = (const float*)d_in[0];
    const float* w_ih = (const float*)d_in[1];
    const float* w_hh = (const float*)d_in[2];
    const float* b_ih = (const float*)d_in[3];
    const float* b_hh = (const float*)d_in[4];
    const float* w1   = (const float*)d_in[5];
    const float* b1   = (const float*)d_in[6];
    const float* w2   = (const float*)d_in[7];
    const float* b2   = (const float*)d_in[8];
    float* out = (float*)d_out;

    cudaFuncSetAttribute(prnn_kernel, cudaFuncAttributeMaxDynamicSharedMemorySize, SMEM_TOTAL);
    prnn_kernel<<<NCTA, THREADS, SMEM_TOTAL>>>(
        x, w_ih, w_hh, b_ih, b_hh, w1, b1, w2, b2, out);
}